// round 1
// baseline (speedup 1.0000x reference)
#include <cuda_runtime.h>
#include <math.h>

// Problem constants
#define H_    112
#define W_    200
#define HW_   (H_*W_)        // 22400
#define C_    64
#define BN_   6
#define PAD_  4
#define HP_   (H_ + 2*PAD_)  // 120
#define WP_   (W_ + 2*PAD_)  // 208
#define HPWP_ (HP_*WP_)      // 24960
#define NTAP  81

// ---------------- scratch (static device memory; no allocations) ------------
__device__ float4 g_q   [BN_*HW_*16];     // query,  [n][h][w][c] channel-last (16 float4/px)
__device__ float4 g_kpad[BN_*HPWP_*16];   // key,    [n][hp][wp][c] padded channel-last
__device__ float4 g_vpad[BN_*HPWP_*16];   // value,  padded channel-last
__device__ float  g_tmp [BN_*C_*HW_];     // intermediate conv activation (NCHW)
__device__ float  g_Wt  [5*64*64];        // folded weights, [layer][c_in][c_out]
__device__ float  g_bf  [5*64];           // folded bias

// ---------------- BN folding ------------------------------------------------
__global__ void prep_kernel(const float* __restrict__ wc, const float* __restrict__ g,
                            const float* __restrict__ b,  const float* __restrict__ m,
                            const float* __restrict__ v) {
    int idx = blockIdx.x * 256 + threadIdx.x;
    if (idx < 5*64*64) {
        int l  = idx >> 12;
        int r  = idx & 4095;
        int ci = r >> 6;
        int o  = r & 63;
        float s = g[l*64 + o] * rsqrtf(v[l*64 + o] + 1e-5f);
        g_Wt[idx] = s * wc[(l*64 + o)*64 + ci];   // transposed: [ci][o]
    }
    if (idx < 5*64) {
        float s = g[idx] * rsqrtf(v[idx] + 1e-5f);
        g_bf[idx] = b[idx] - s * m[idx];
    }
}

// ---------------- zero the padded K/V buffers -------------------------------
__global__ void zero_pads_kernel() {
    const int total = BN_*HPWP_*16;
    float4 z = make_float4(0.f, 0.f, 0.f, 0.f);
    for (int j = blockIdx.x*blockDim.x + threadIdx.x; j < total; j += gridDim.x*blockDim.x) {
        g_kpad[j] = z;
        g_vpad[j] = z;
    }
}

// ---------------- 1x1 conv + (folded) BN + ReLU -----------------------------
// Tile: 64 pixels x 64 out-channels per 128-thread block.
// Thread (tp = tid&15, to = tid>>4) computes 8 outs x 4 px.
// mode 0: NCHW output.  mode 1: channel-last output with spatial pad.
__global__ __launch_bounds__(128) void conv_kernel(
    const float* __restrict__ in, int layer, float* __restrict__ out,
    int mode, int pad, int Hp, int Wp)
{
    __shared__ float ws[4096];     // weights [ci][o]
    __shared__ float xs[16*64];    // x chunk [ci(16)][px(64)]
    const int tid = threadIdx.x;
    const int tp = tid & 15;
    const int to = tid >> 4;
    const int n  = blockIdx.y;
    const int p0 = blockIdx.x * 64;

    const float* wsrc = g_Wt + layer*4096;
    #pragma unroll
    for (int i = 0; i < 32; i++) ws[i*128 + tid] = wsrc[i*128 + tid];

    const float* inb = in + (size_t)n*C_*HW_ + p0;

    float acc[8][4];
    #pragma unroll
    for (int oi = 0; oi < 8; oi++)
        #pragma unroll
        for (int pj = 0; pj < 4; pj++) acc[oi][pj] = 0.f;

    const float4* ws4 = (const float4*)ws;
    const float4* xs4 = (const float4*)xs;

    for (int cc = 0; cc < 4; cc++) {
        __syncthreads();
        #pragma unroll
        for (int r = 0; r < 8; r++) {
            int lin = r*128 + tid;          // lin = ci*64 + px
            int ci  = lin >> 6;
            int px  = lin & 63;
            xs[lin] = inb[(cc*16 + ci)*HW_ + px];
        }
        __syncthreads();
        #pragma unroll
        for (int ci = 0; ci < 16; ci++) {
            float4 xv = xs4[ci*16 + tp];
            float4 wa = ws4[(cc*16 + ci)*16 + to*2];
            float4 wb = ws4[(cc*16 + ci)*16 + to*2 + 1];
            float wv[8] = {wa.x, wa.y, wa.z, wa.w, wb.x, wb.y, wb.z, wb.w};
            float xp[4] = {xv.x, xv.y, xv.z, xv.w};
            #pragma unroll
            for (int oi = 0; oi < 8; oi++)
                #pragma unroll
                for (int pj = 0; pj < 4; pj++)
                    acc[oi][pj] += wv[oi] * xp[pj];
        }
    }

    // bias + relu
    #pragma unroll
    for (int oi = 0; oi < 8; oi++) {
        float bb = g_bf[layer*64 + to*8 + oi];
        #pragma unroll
        for (int pj = 0; pj < 4; pj++)
            acc[oi][pj] = fmaxf(acc[oi][pj] + bb, 0.f);
    }

    if (mode == 0) {
        float* ob = out + (size_t)n*C_*HW_ + p0 + tp*4;
        #pragma unroll
        for (int oi = 0; oi < 8; oi++) {
            float4 vv = make_float4(acc[oi][0], acc[oi][1], acc[oi][2], acc[oi][3]);
            *(float4*)&ob[(to*8 + oi)*HW_] = vv;
        }
    } else {
        #pragma unroll
        for (int pj = 0; pj < 4; pj++) {
            int px = p0 + tp*4 + pj;
            int h = px / W_;
            int w = px - h*W_;
            float* ob = out + (((size_t)(n*Hp + h + pad))*Wp + (w + pad))*64 + to*8;
            *(float4*)ob       = make_float4(acc[0][pj], acc[1][pj], acc[2][pj], acc[3][pj]);
            *(float4*)(ob + 4) = make_float4(acc[4][pj], acc[5][pj], acc[6][pj], acc[7][pj]);
        }
    }
}

// ---------------- fused similarity + softmax + weighting --------------------
// 32x8 pixel tile, 256 threads, 1 pixel/thread, acc[81] in registers.
// K/V halos staged per 16-channel group: hs[c4][row(16)][col(41)] of float4.
__global__ __launch_bounds__(256, 2) void attn_kernel(float* __restrict__ out)
{
    __shared__ float4 hs[4][16][41];
    const int tid = threadIdx.x;
    const int tx = tid & 31;
    const int ty = tid >> 5;
    const int w0 = blockIdx.x * 32;
    const int h0 = blockIdx.y * 8;
    const int n  = blockIdx.z;
    const int w = w0 + tx;
    const int h = h0 + ty;
    const bool valid = (w < W_);
    const int qpx = (n*H_ + h)*W_ + (valid ? w : 0);

    float acc[NTAP];
    #pragma unroll
    for (int t = 0; t < NTAP; t++) acc[t] = 0.f;

    // ---- phase 1: local similarity ----
    for (int g = 0; g < 4; g++) {
        __syncthreads();
        #pragma unroll
        for (int i = 0; i < 10; i++) {
            int lin = i*256 + tid;             // 2560 float4 total
            int c   = lin & 3;
            int col = (lin >> 2) % 40;
            int r   = lin / 160;
            int wp  = w0 + col;
            float4 val = make_float4(0.f, 0.f, 0.f, 0.f);
            if (wp < WP_)
                val = g_kpad[((size_t)(n*HP_ + h0 + r)*WP_ + wp)*16 + g*4 + c];
            hs[c][r][col] = val;
        }
        __syncthreads();
        #pragma unroll
        for (int c4 = 0; c4 < 4; c4++) {
            float4 qv = g_q[(size_t)qpx*16 + g*4 + c4];
            const float4* hb = &hs[c4][ty][tx];
            #pragma unroll
            for (int di = 0; di < 9; di++)
                #pragma unroll
                for (int dj = 0; dj < 9; dj++) {
                    float4 kv = hb[di*41 + dj];
                    acc[di*9 + dj] += qv.x*kv.x + qv.y*kv.y + qv.z*kv.z + qv.w*kv.w;
                }
        }
    }

    // ---- softmax over 81 taps (scale by 1/sqrt(64)) ----
    float mx = acc[0];
    #pragma unroll
    for (int t = 1; t < NTAP; t++) mx = fmaxf(mx, acc[t]);
    float sum = 0.f;
    #pragma unroll
    for (int t = 0; t < NTAP; t++) {
        float e = __expf((acc[t] - mx) * 0.125f);
        acc[t] = e;
        sum += e;
    }
    float inv = 1.f / sum;
    #pragma unroll
    for (int t = 0; t < NTAP; t++) acc[t] *= inv;

    // ---- phase 2: local weighting of V ----
    for (int g = 0; g < 4; g++) {
        __syncthreads();
        #pragma unroll
        for (int i = 0; i < 10; i++) {
            int lin = i*256 + tid;
            int c   = lin & 3;
            int col = (lin >> 2) % 40;
            int r   = lin / 160;
            int wp  = w0 + col;
            float4 val = make_float4(0.f, 0.f, 0.f, 0.f);
            if (wp < WP_)
                val = g_vpad[((size_t)(n*HP_ + h0 + r)*WP_ + wp)*16 + g*4 + c];
            hs[c][r][col] = val;
        }
        __syncthreads();
        #pragma unroll
        for (int c4 = 0; c4 < 4; c4++) {
            float4 ov = make_float4(0.f, 0.f, 0.f, 0.f);
            const float4* hb = &hs[c4][ty][tx];
            #pragma unroll
            for (int di = 0; di < 9; di++)
                #pragma unroll
                for (int dj = 0; dj < 9; dj++) {
                    float4 vv = hb[di*41 + dj];
                    float wt = acc[di*9 + dj];
                    ov.x += wt*vv.x; ov.y += wt*vv.y; ov.z += wt*vv.z; ov.w += wt*vv.w;
                }
            if (valid) {
                int cbase = g*16 + c4*4;
                float* ob = out + ((size_t)(n*C_ + cbase)*H_ + h)*W_ + w;
                ob[0]       = ov.x;
                ob[HW_]     = ov.y;
                ob[2*HW_]   = ov.z;
                ob[3*HW_]   = ov.w;
            }
        }
    }
}

// ---------------- launch ----------------------------------------------------
extern "C" void kernel_launch(void* const* d_in, const int* in_sizes, int n_in,
                              void* d_out, int out_size)
{
    (void)in_sizes; (void)n_in; (void)out_size;
    const float* img  = (const float*)d_in[0];
    const float* wimg = (const float*)d_in[1];
    const float* wc   = (const float*)d_in[2];
    const float* gg   = (const float*)d_in[3];
    const float* bb   = (const float*)d_in[4];
    const float* mm   = (const float*)d_in[5];
    const float* vv   = (const float*)d_in[6];
    float* out = (float*)d_out;

    float *p_tmp, *p_q, *p_kpad, *p_vpad;
    cudaGetSymbolAddress((void**)&p_tmp,  g_tmp);
    cudaGetSymbolAddress((void**)&p_q,    g_q);
    cudaGetSymbolAddress((void**)&p_kpad, g_kpad);
    cudaGetSymbolAddress((void**)&p_vpad, g_vpad);

    prep_kernel<<<80, 256>>>(wc, gg, bb, mm, vv);
    zero_pads_kernel<<<2048, 256>>>();

    dim3 cgrid(HW_/64, BN_);   // 350 x 6
    // query = CBR1(CBR0(img))
    conv_kernel<<<cgrid, 128>>>(img,   0, p_tmp, 0, 0, 0, 0);
    conv_kernel<<<cgrid, 128>>>(p_tmp, 1, p_q,   1, 0, H_, W_);
    // key = CBR3(CBR2(wimg))   (padded channel-last)
    conv_kernel<<<cgrid, 128>>>(wimg,  2, p_tmp, 0, 0, 0, 0);
    conv_kernel<<<cgrid, 128>>>(p_tmp, 3, p_kpad, 1, PAD_, HP_, WP_);
    // value = CBR4(wimg)       (padded channel-last)
    conv_kernel<<<cgrid, 128>>>(wimg,  4, p_vpad, 1, PAD_, HP_, WP_);

    dim3 agrid((W_ + 31)/32, H_/8, BN_);   // 7 x 14 x 6
    attn_kernel<<<agrid, 256>>>(out);
}